// round 12
// baseline (speedup 1.0000x reference)
#include <cuda_runtime.h>
#include <cuda_fp16.h>
#include <cstdint>

#define NUM_TOKENS 4096
#define NUM_EXPERTS 16
#define HIDDEN 2880
#define INTER 2880
#define N1 (2 * INTER)          /* 5760 */
#define ROWS (NUM_TOKENS * 2)

#define BM 128
#define BN1 64
#define BN2 96
#define BK 64
#define NC (HIDDEN / BK)        /* 45 */
#define NT1 (INTER / BN1)       /* 45 */
#define NT2 (HIDDEN / BN2)      /* 30 */
#define MAXTILES 80
#define CVT_SLICES 16           /* extra blockIdx.y slices in GEMM1 that convert w2 */

#define PITCHB 144
#define A_BYTES (BM * PITCHB)   /* 18432 */
#define B1_BYTES (BN1 * PITCHB) /* 9216 */
#define B2_BYTES (BN2 * PITCHB) /* 13824 */
#define STG1 (A_BYTES + 2 * B1_BYTES)  /* 36864 */
#define STG2 (A_BYTES + B2_BYTES)      /* 32256 */
#define G1_SMEM (1024 + 3 * STG1)      /* 111616 */
#define G2_SMEM (1024 + 3 * STG2)      /* 97792 */

// ---------------- device scratch ----------------------------------------------
__device__ __align__(256) __half g_w13h[(size_t)NUM_EXPERTS * N1 * HIDDEN];
__device__ __align__(256) __half g_w2h[(size_t)NUM_EXPERTS * HIDDEN * INTER];
__device__ __align__(256) __half g_hsh[(size_t)NUM_TOKENS * HIDDEN];
__device__ __align__(256) __half g_acth[(size_t)ROWS * INTER];
__device__ int   g_rowmap[ROWS];
__device__ float g_gate_by_row[ROWS];
__device__ float g_gate_of[NUM_TOKENS * 2];
__device__ int   g_expert_of[NUM_TOKENS * 2];
__device__ int   g_counts[NUM_EXPERTS];
__device__ int   g_offsets[NUM_EXPERTS + 1];
__device__ int   g_cursor[NUM_EXPERTS];
__device__ int   g_ntiles;
__device__ int   g_tile_e[MAXTILES];
__device__ int   g_tile_m0[MAXTILES];

// ---------------- helpers ------------------------------------------------------
__device__ __forceinline__ uint32_t h2u(float a, float b) {
    __half2 h = __floats2half2_rn(a, b);
    return *reinterpret_cast<uint32_t*>(&h);
}
__device__ __forceinline__ uint32_t smem_u32(const void* p) {
    uint32_t a;
    asm("{ .reg .u64 t; cvta.to.shared.u64 t, %1; cvt.u32.u64 %0, t; }"
        : "=r"(a) : "l"(p));
    return a;
}
#define CP16(dst, src) \
    asm volatile("cp.async.cg.shared.global [%0], [%1], 16;" :: "r"(dst), "l"(src))
#define CP_COMMIT() asm volatile("cp.async.commit_group;" ::: "memory")
#define CP_WAIT1()  asm volatile("cp.async.wait_group 1;" ::: "memory")

__device__ __forceinline__ void ldsm4(uint32_t& r0, uint32_t& r1, uint32_t& r2,
                                      uint32_t& r3, uint32_t addr) {
    asm volatile("ldmatrix.sync.aligned.m8n8.x4.shared.b16 {%0,%1,%2,%3}, [%4];"
                 : "=r"(r0), "=r"(r1), "=r"(r2), "=r"(r3) : "r"(addr));
}
__device__ __forceinline__ void mma16816(float* c, uint32_t a0, uint32_t a1,
                                         uint32_t a2, uint32_t a3,
                                         uint32_t b0, uint32_t b1) {
    asm volatile(
        "mma.sync.aligned.m16n8k16.row.col.f32.f16.f16.f32 "
        "{%0,%1,%2,%3}, {%4,%5,%6,%7}, {%8,%9}, {%0,%1,%2,%3};"
        : "+f"(c[0]), "+f"(c[1]), "+f"(c[2]), "+f"(c[3])
        : "r"(a0), "r"(a1), "r"(a2), "r"(a3), "r"(b0), "r"(b1));
}
__device__ __forceinline__ float silu(float x) {
    return x / (1.0f + __expf(-x));
}
__device__ __forceinline__ uint2 cvt4(const float4& v) {
    uint2 o;
    o.x = h2u(v.x, v.y);
    o.y = h2u(v.z, v.w);
    return o;
}

// ---------------- routing (single CTA) -------------------------------------------
__global__ void k_routing(const float* __restrict__ logits) {
    int tid = threadIdx.x;
    if (tid < NUM_EXPERTS) { g_counts[tid] = 0; g_cursor[tid] = 0; }
    __syncthreads();

    for (int t = tid; t < NUM_TOKENS; t += 256) {
        const float* l = logits + (size_t)t * NUM_EXPERTS;
        float v[NUM_EXPERTS];
#pragma unroll
        for (int e = 0; e < NUM_EXPERTS; e++) v[e] = l[e];
        int i1 = 0; float v1 = v[0];
#pragma unroll
        for (int e = 1; e < NUM_EXPERTS; e++) if (v[e] > v1) { v1 = v[e]; i1 = e; }
        int i2 = -1; float v2 = -1e30f;
#pragma unroll
        for (int e = 0; e < NUM_EXPERTS; e++)
            if (e != i1 && v[e] > v2) { v2 = v[e]; i2 = e; }
        float g1 = 1.0f / (1.0f + expf(v2 - v1));
        g_expert_of[2 * t + 0] = i1;  g_gate_of[2 * t + 0] = g1;
        g_expert_of[2 * t + 1] = i2;  g_gate_of[2 * t + 1] = 1.0f - g1;
        atomicAdd(&g_counts[i1], 1);
        atomicAdd(&g_counts[i2], 1);
    }
    __syncthreads();

    if (tid == 0) {
        int acc = 0;
        for (int e = 0; e < NUM_EXPERTS; e++) { g_offsets[e] = acc; acc += g_counts[e]; }
        g_offsets[NUM_EXPERTS] = acc;
        int nt = 0;
        for (int e = 0; e < NUM_EXPERTS; e++) {
            int cnt = g_counts[e];
            for (int m0 = 0; m0 < cnt; m0 += BM) {
                g_tile_e[nt] = e;
                g_tile_m0[nt] = m0;
                nt++;
            }
        }
        g_ntiles = nt;
    }
    __syncthreads();

    for (int t = tid; t < NUM_TOKENS; t += 256) {
#pragma unroll
        for (int k = 0; k < 2; k++) {
            int e = g_expert_of[2 * t + k];
            int pos = g_offsets[e] + atomicAdd(&g_cursor[e], 1);
            g_rowmap[pos] = t;
            g_gate_by_row[pos] = g_gate_of[2 * t + k];
        }
    }
}

// ---------------- fp32 -> fp16 (4-way ILP, streaming) / zero-out ------------------
__global__ void k_cvt4(const float4* __restrict__ src, uint2* __restrict__ dst,
                       size_t quarter) {      // processes 4*quarter float4s
    size_t i = (size_t)blockIdx.x * blockDim.x + threadIdx.x;
    if (i >= quarter) return;
    float4 v0 = __ldcs(&src[i]);
    float4 v1 = __ldcs(&src[i + quarter]);
    float4 v2 = __ldcs(&src[i + 2 * quarter]);
    float4 v3 = __ldcs(&src[i + 3 * quarter]);
    __stcg(&dst[i],               cvt4(v0));
    __stcg(&dst[i + quarter],     cvt4(v1));
    __stcg(&dst[i + 2 * quarter], cvt4(v2));
    __stcg(&dst[i + 3 * quarter], cvt4(v3));
}
__global__ void k_zero(float4* __restrict__ out) {
    size_t i = (size_t)blockIdx.x * blockDim.x + threadIdx.x;
    if (i < (size_t)NUM_TOKENS * HIDDEN / 4)
        out[i] = make_float4(0.f, 0.f, 0.f, 0.f);
}

// ---------------- GEMM1: act = silu(X@Wg^T+bg) * (X@Wu^T+bu) -------------------
// Extra blockIdx.y slices [MAXTILES, MAXTILES+CVT_SLICES) convert w2 fp32->fp16
// concurrently (GEMM1 does not read g_w2h; GEMM2 runs after this kernel).
__global__ __launch_bounds__(256, 2) void k_gemm1(const float* __restrict__ w13b,
                                                  const float4* __restrict__ w2src) {
    int ty = blockIdx.y;
    int tid = threadIdx.x;

    if (ty >= MAXTILES) {                    // w2 conversion CTA (streaming hints)
        const size_t n4 = (size_t)NUM_EXPERTS * HIDDEN * INTER / 4;
        const size_t stride = (size_t)CVT_SLICES * NT1 * 256;
        size_t i = ((size_t)(ty - MAXTILES) * gridDim.x + blockIdx.x) * 256 + tid;
        uint2* dst = (uint2*)g_w2h;
        for (; i < n4; i += stride) {
            float4 v = __ldcs(&w2src[i]);
            __stcg(&dst[i], cvt4(v));
        }
        return;
    }
    if (ty >= g_ntiles) return;

    extern __shared__ __align__(128) uint8_t smem[];
    int* stok = (int*)smem;
    float* sbias = (float*)(smem + 512);
    uint32_t sb = smem_u32(smem);
    uint32_t stage0 = sb + 1024;

    int e = g_tile_e[ty];
    int m0 = g_tile_m0[ty];
    int seg0 = g_offsets[e];
    int cnt  = g_offsets[e + 1] - seg0;
    int n0 = blockIdx.x * BN1;
    int wid = tid >> 5, lid = tid & 31;
    int warpM = wid & 3, warpN = wid >> 2;

    if (tid < BM) {
        int m = m0 + tid;
        stok[tid] = g_rowmap[seg0 + (m < cnt ? m : cnt - 1)];
    }
    if (tid >= 128 && tid < 192)
        sbias[tid - 128] = w13b[(size_t)e * N1 + n0 + (tid - 128)];
    else if (tid >= 192)
        sbias[tid - 192 + 64] = w13b[(size_t)e * N1 + INTER + n0 + (tid - 192)];
    __syncthreads();

    const __half* wg = g_w13h + (size_t)e * N1 * HIDDEN + (size_t)n0 * HIDDEN;
    const __half* wu = g_w13h + (size_t)e * N1 * HIDDEN + (size_t)(INTER + n0) * HIDDEN;

    auto load_stage = [&](int s, int c) {
        uint32_t st = stage0 + s * STG1;
        int k0 = c * BK;
#pragma unroll
        for (int q = 0; q < 8; q++) {
            int ch = tid + q * 256;
            if (ch < 1024) {
                int r = ch >> 3, c8 = ch & 7;
                const __half* src = g_hsh + (size_t)stok[r] * HIDDEN + k0 + c8 * 8;
                CP16(st + r * PITCHB + c8 * 16, src);
            } else if (ch < 1536) {
                int i = ch - 1024, r = i >> 3, c8 = i & 7;
                const __half* src = wg + (size_t)r * HIDDEN + k0 + c8 * 8;
                CP16(st + A_BYTES + r * PITCHB + c8 * 16, src);
            } else {
                int i = ch - 1536, r = i >> 3, c8 = i & 7;
                const __half* src = wu + (size_t)r * HIDDEN + k0 + c8 * 8;
                CP16(st + A_BYTES + B1_BYTES + r * PITCHB + c8 * 16, src);
            }
        }
        CP_COMMIT();
    };

    float accG[2][4][4], accU[2][4][4];
#pragma unroll
    for (int i = 0; i < 2; i++)
#pragma unroll
        for (int j = 0; j < 4; j++)
#pragma unroll
            for (int q = 0; q < 4; q++) { accG[i][j][q] = 0.f; accU[i][j][q] = 0.f; }

    load_stage(0, 0);
    load_stage(1, 1);

    int lrow = lid & 15;
    int lcolb = (lid & 16);

    for (int c = 0; c < NC; c++) {
        CP_WAIT1();
        __syncthreads();
        if (c + 2 < NC) load_stage((c + 2) % 3, c + 2);
        else CP_COMMIT();
        uint32_t st = stage0 + (c % 3) * STG1;
        uint32_t aBase = st + (warpM * 32 + lrow) * PITCHB + lcolb;
        uint32_t gBase = st + A_BYTES + (warpN * 32 + lrow) * PITCHB + lcolb;
        uint32_t uBase = gBase + B1_BYTES;
#pragma unroll
        for (int kk = 0; kk < 4; kk++) {
            uint32_t koff = kk * 32;
            uint32_t a[2][4];
            ldsm4(a[0][0], a[0][1], a[0][2], a[0][3], aBase + koff);
            ldsm4(a[1][0], a[1][1], a[1][2], a[1][3], aBase + 16 * PITCHB + koff);
#pragma unroll
            for (int ntp = 0; ntp < 2; ntp++) {
                uint32_t b0, b1, b2, b3;
                ldsm4(b0, b1, b2, b3, gBase + ntp * 16 * PITCHB + koff);
#pragma unroll
                for (int mt = 0; mt < 2; mt++) {
                    mma16816(accG[mt][2 * ntp + 0], a[mt][0], a[mt][1], a[mt][2], a[mt][3], b0, b2);
                    mma16816(accG[mt][2 * ntp + 1], a[mt][0], a[mt][1], a[mt][2], a[mt][3], b1, b3);
                }
                ldsm4(b0, b1, b2, b3, uBase + ntp * 16 * PITCHB + koff);
#pragma unroll
                for (int mt = 0; mt < 2; mt++) {
                    mma16816(accU[mt][2 * ntp + 0], a[mt][0], a[mt][1], a[mt][2], a[mt][3], b0, b2);
                    mma16816(accU[mt][2 * ntp + 1], a[mt][0], a[mt][1], a[mt][2], a[mt][3], b1, b3);
                }
            }
        }
    }

    int g = lid >> 2, t = lid & 3;
#pragma unroll
    for (int mt = 0; mt < 2; mt++) {
#pragma unroll
        for (int nt = 0; nt < 4; nt++) {
            int ncol = warpN * 32 + nt * 8 + 2 * t;
            float bg0 = sbias[ncol], bg1 = sbias[ncol + 1];
            float bu0 = sbias[64 + ncol], bu1 = sbias[64 + ncol + 1];
            int mA = m0 + warpM * 32 + mt * 16 + g;
            int mB = mA + 8;
            if (mA < cnt) {
                float a0 = silu(accG[mt][nt][0] + bg0) * (accU[mt][nt][0] + bu0);
                float a1 = silu(accG[mt][nt][1] + bg1) * (accU[mt][nt][1] + bu1);
                *(uint32_t*)(g_acth + (size_t)(seg0 + mA) * INTER + n0 + ncol) = h2u(a0, a1);
            }
            if (mB < cnt) {
                float a2 = silu(accG[mt][nt][2] + bg0) * (accU[mt][nt][2] + bu0);
                float a3 = silu(accG[mt][nt][3] + bg1) * (accU[mt][nt][3] + bu1);
                *(uint32_t*)(g_acth + (size_t)(seg0 + mB) * INTER + n0 + ncol) = h2u(a2, a3);
            }
        }
    }
}

// ---------------- GEMM2: out += gate * (act @ W2^T + b2), fused combine ----------
__global__ __launch_bounds__(256, 2) void k_gemm2(const float* __restrict__ w2b,
                                                  float* __restrict__ out) {
    extern __shared__ __align__(128) uint8_t smem[];
    float* sbias = (float*)(smem + 512);
    uint32_t sb = smem_u32(smem);
    uint32_t stage0 = sb + 1024;

    int ty = blockIdx.y;
    if (ty >= g_ntiles) return;
    int e = g_tile_e[ty];
    int m0 = g_tile_m0[ty];
    int seg0 = g_offsets[e];
    int cnt  = g_offsets[e + 1] - seg0;
    int n0 = blockIdx.x * BN2;
    int tid = threadIdx.x, wid = tid >> 5, lid = tid & 31;
    int warpM = wid & 3, warpN = wid >> 2;

    if (tid < BN2) sbias[tid] = w2b[(size_t)e * HIDDEN + n0 + tid];
    __syncthreads();

    const __half* wb = g_w2h + (size_t)e * HIDDEN * INTER + (size_t)n0 * INTER;
    const __half* aext = g_acth + (size_t)seg0 * INTER;
    int mclamp = cnt - 1;

    auto load_stage = [&](int s, int c) {
        uint32_t st = stage0 + s * STG2;
        int k0 = c * BK;
#pragma unroll
        for (int q = 0; q < 7; q++) {
            int ch = tid + q * 256;
            if (ch < 1024) {
                int r = ch >> 3, c8 = ch & 7;
                int m = m0 + r; if (m > mclamp) m = mclamp;
                const __half* src = aext + (size_t)m * INTER + k0 + c8 * 8;
                CP16(st + r * PITCHB + c8 * 16, src);
            } else {
                int i = ch - 1024, r = i >> 3, c8 = i & 7;
                const __half* src = wb + (size_t)r * INTER + k0 + c8 * 8;
                CP16(st + A_BYTES + r * PITCHB + c8 * 16, src);
            }
        }
        CP_COMMIT();
    };

    float acc[2][6][4];
#pragma unroll
    for (int i = 0; i < 2; i++)
#pragma unroll
        for (int j = 0; j < 6; j++)
#pragma unroll
            for (int q = 0; q < 4; q++) acc[i][j][q] = 0.f;

    load_stage(0, 0);
    load_stage(1, 1);

    int lrow = lid & 15;
    int lcolb = (lid & 16);

    for (int c = 0; c < NC; c++) {
        CP_WAIT1();
        __syncthreads();
        if (c + 2 < NC) load_stage((c + 2) % 3, c + 2);
        else CP_COMMIT();
        uint32_t st = stage0 + (c % 3) * STG2;
        uint32_t aBase = st + (warpM * 32 + lrow) * PITCHB + lcolb;
        uint32_t bBase = st + A_BYTES + (warpN * 48 + lrow) * PITCHB + lcolb;
#pragma unroll
        for (int kk = 0; kk < 4; kk++) {
            uint32_t koff = kk * 32;
            uint32_t a[2][4];
            ldsm4(a[0][0], a[0][1], a[0][2], a[0][3], aBase + koff);
            ldsm4(a[1][0], a[1][1], a[1][2], a[1][3], aBase + 16 * PITCHB + koff);
#pragma unroll
            for (int ntp = 0; ntp < 3; ntp++) {
                uint32_t b0, b1, b2, b3;
                ldsm4(b0, b1, b2, b3, bBase + ntp * 16 * PITCHB + koff);
#pragma unroll
                for (int mt = 0; mt < 2; mt++) {
                    mma16816(acc[mt][2 * ntp + 0], a[mt][0], a[mt][1], a[mt][2], a[mt][3], b0, b2);
                    mma16816(acc[mt][2 * ntp + 1], a[mt][0], a[mt][1], a[mt][2], a[mt][3], b1, b3);
                }
            }
        }
    }

    int g = lid >> 2, t = lid & 3;
#pragma unroll
    for (int mt = 0; mt < 2; mt++) {
        int mA = m0 + warpM * 32 + mt * 16 + g;
        int mB = mA + 8;
        int tokA = 0, tokB = 0;
        float gA = 0.f, gB = 0.f;
        if (mA < cnt) { tokA = g_rowmap[seg0 + mA]; gA = g_gate_by_row[seg0 + mA]; }
        if (mB < cnt) { tokB = g_rowmap[seg0 + mB]; gB = g_gate_by_row[seg0 + mB]; }
#pragma unroll
        for (int nt = 0; nt < 6; nt++) {
            int ncol = warpN * 48 + nt * 8 + 2 * t;
            float b0 = sbias[ncol], b1 = sbias[ncol + 1];
            if (mA < cnt) {
                float* d = out + (size_t)tokA * HIDDEN + n0 + ncol;
                atomicAdd(d + 0, gA * (acc[mt][nt][0] + b0));
                atomicAdd(d + 1, gA * (acc[mt][nt][1] + b1));
            }
            if (mB < cnt) {
                float* d = out + (size_t)tokB * HIDDEN + n0 + ncol;
                atomicAdd(d + 0, gB * (acc[mt][nt][2] + b0));
                atomicAdd(d + 1, gB * (acc[mt][nt][3] + b1));
            }
        }
    }
}

// ---------------- launch ---------------------------------------------------------
extern "C" void kernel_launch(void* const* d_in, const int* in_sizes, int n_in,
                              void* d_out, int out_size)
{
    const float* hs   = (const float*)d_in[0];
    const float* rl   = (const float*)d_in[1];
    const float* w13  = (const float*)d_in[2];
    const float* w2   = (const float*)d_in[3];
    const float* w13b = (const float*)d_in[4];
    const float* w2b  = (const float*)d_in[5];
    float* out = (float*)d_out;

    static bool attr_done = false;
    if (!attr_done) {
        cudaFuncSetAttribute(k_gemm1, cudaFuncAttributeMaxDynamicSharedMemorySize, G1_SMEM);
        cudaFuncSetAttribute(k_gemm2, cudaFuncAttributeMaxDynamicSharedMemorySize, G2_SMEM);
        attr_done = true;
    }

    k_routing<<<1, 256>>>(rl);

    {
        size_t n4 = (size_t)NUM_TOKENS * HIDDEN / 4;
        k_zero<<<(unsigned)((n4 + 255) / 256), 256>>>((float4*)out);
    }

    __half* w13h_ptr = nullptr;  cudaGetSymbolAddress((void**)&w13h_ptr, g_w13h);
    __half* hsh_ptr  = nullptr;  cudaGetSymbolAddress((void**)&hsh_ptr,  g_hsh);

    {   // w13 convert: 4-way ILP + streaming hints
        size_t quarter = (size_t)NUM_EXPERTS * N1 * HIDDEN / 16;
        k_cvt4<<<(unsigned)((quarter + 255) / 256), 256>>>((const float4*)w13,
                                                           (uint2*)w13h_ptr, quarter);
    }
    {   // hs convert
        size_t quarter = (size_t)NUM_TOKENS * HIDDEN / 16;
        k_cvt4<<<(unsigned)((quarter + 255) / 256), 256>>>((const float4*)hs,
                                                           (uint2*)hsh_ptr, quarter);
    }

    {   // GEMM1 + concurrent w2 conversion (extra y-slices)
        dim3 grid(NT1, MAXTILES + CVT_SLICES);
        k_gemm1<<<grid, 256, G1_SMEM>>>(w13b, (const float4*)w2);
    }
    {   // GEMM2 with fused gate-combine into out
        dim3 grid(NT2, MAXTILES);
        k_gemm2<<<grid, 256, G2_SMEM>>>(w2b, out);
    }
}

// round 13
// speedup vs baseline: 1.0822x; 1.0822x over previous
#include <cuda_runtime.h>
#include <cuda_fp16.h>
#include <cstdint>

#define NUM_TOKENS 4096
#define NUM_EXPERTS 16
#define HIDDEN 2880
#define INTER 2880
#define N1 (2 * INTER)          /* 5760 */
#define ROWS (NUM_TOKENS * 2)   /* 8192 expanded rows */

#define BM 128
#define BN1 64                  /* GEMM1 N tile (per gate/up) */
#define BN2 96                  /* GEMM2 N tile */
#define BK 64                   /* K chunk, halves */
#define NC (HIDDEN / BK)        /* 45 k-iterations */
#define NT1 (INTER / BN1)       /* 45 */
#define NT2 (HIDDEN / BN2)      /* 30 */
#define MAXTILES 80             /* sum ceil(cnt/128) <= 64 + 16 */
#define CVT_SLICES 16           /* extra blockIdx.y slices in GEMM1 that convert w2 */

#define PITCHB 144              /* 64 halves = 128B + 16B pad */
#define A_BYTES (BM * PITCHB)   /* 18432 */
#define B1_BYTES (BN1 * PITCHB) /* 9216 */
#define B2_BYTES (BN2 * PITCHB) /* 13824 */
#define STG1 (A_BYTES + 2 * B1_BYTES)  /* 36864 */
#define STG2 (A_BYTES + B2_BYTES)      /* 32256 */
#define G1_SMEM (1024 + 3 * STG1)      /* 111616 */
#define G2_SMEM (1024 + 3 * STG2)      /* 97792 */

// ---------------- device scratch ----------------------------------------------
__device__ __align__(256) __half g_w13h[(size_t)NUM_EXPERTS * N1 * HIDDEN];
__device__ __align__(256) __half g_w2h[(size_t)NUM_EXPERTS * HIDDEN * INTER];
__device__ __align__(256) __half g_hsh[(size_t)NUM_TOKENS * HIDDEN];
__device__ __align__(256) __half g_acth[(size_t)ROWS * INTER];
__device__ int   g_rowmap[ROWS];
__device__ float g_gate_by_row[ROWS];
__device__ float g_gate_of[NUM_TOKENS * 2];
__device__ int   g_expert_of[NUM_TOKENS * 2];
__device__ int   g_counts[NUM_EXPERTS];
__device__ int   g_offsets[NUM_EXPERTS + 1];
__device__ int   g_cursor[NUM_EXPERTS];
__device__ int   g_ntiles;
__device__ int   g_tile_e[MAXTILES];
__device__ int   g_tile_m0[MAXTILES];

// ---------------- helpers ------------------------------------------------------
__device__ __forceinline__ uint32_t h2u(float a, float b) {
    __half2 h = __floats2half2_rn(a, b);
    return *reinterpret_cast<uint32_t*>(&h);
}
__device__ __forceinline__ uint32_t smem_u32(const void* p) {
    uint32_t a;
    asm("{ .reg .u64 t; cvta.to.shared.u64 t, %1; cvt.u32.u64 %0, t; }"
        : "=r"(a) : "l"(p));
    return a;
}
#define CP16(dst, src) \
    asm volatile("cp.async.cg.shared.global [%0], [%1], 16;" :: "r"(dst), "l"(src))
#define CP_COMMIT() asm volatile("cp.async.commit_group;" ::: "memory")
#define CP_WAIT1()  asm volatile("cp.async.wait_group 1;" ::: "memory")

__device__ __forceinline__ void ldsm4(uint32_t& r0, uint32_t& r1, uint32_t& r2,
                                      uint32_t& r3, uint32_t addr) {
    asm volatile("ldmatrix.sync.aligned.m8n8.x4.shared.b16 {%0,%1,%2,%3}, [%4];"
                 : "=r"(r0), "=r"(r1), "=r"(r2), "=r"(r3) : "r"(addr));
}
__device__ __forceinline__ void mma16816(float* c, uint32_t a0, uint32_t a1,
                                         uint32_t a2, uint32_t a3,
                                         uint32_t b0, uint32_t b1) {
    asm volatile(
        "mma.sync.aligned.m16n8k16.row.col.f32.f16.f16.f32 "
        "{%0,%1,%2,%3}, {%4,%5,%6,%7}, {%8,%9}, {%0,%1,%2,%3};"
        : "+f"(c[0]), "+f"(c[1]), "+f"(c[2]), "+f"(c[3])
        : "r"(a0), "r"(a1), "r"(a2), "r"(a3), "r"(b0), "r"(b1));
}
__device__ __forceinline__ float silu(float x) {
    return x / (1.0f + __expf(-x));
}

// ---------------- routing ----------------------------------------------------
__global__ void k_init() {
    int i = threadIdx.x;
    if (i < NUM_EXPERTS) { g_counts[i] = 0; g_cursor[i] = 0; }
}
__global__ void k_route(const float* __restrict__ logits) {
    int t = blockIdx.x * blockDim.x + threadIdx.x;
    if (t >= NUM_TOKENS) return;
    const float* l = logits + (size_t)t * NUM_EXPERTS;
    float v[NUM_EXPERTS];
#pragma unroll
    for (int e = 0; e < NUM_EXPERTS; e++) v[e] = l[e];
    int i1 = 0; float v1 = v[0];
#pragma unroll
    for (int e = 1; e < NUM_EXPERTS; e++) if (v[e] > v1) { v1 = v[e]; i1 = e; }
    int i2 = -1; float v2 = -1e30f;
#pragma unroll
    for (int e = 0; e < NUM_EXPERTS; e++)
        if (e != i1 && v[e] > v2) { v2 = v[e]; i2 = e; }
    float g1 = 1.0f / (1.0f + expf(v2 - v1));
    g_expert_of[2 * t + 0] = i1;  g_gate_of[2 * t + 0] = g1;
    g_expert_of[2 * t + 1] = i2;  g_gate_of[2 * t + 1] = 1.0f - g1;
    atomicAdd(&g_counts[i1], 1);
    atomicAdd(&g_counts[i2], 1);
}
__global__ void k_scan() {
    if (threadIdx.x == 0) {
        int acc = 0;
        for (int e = 0; e < NUM_EXPERTS; e++) { g_offsets[e] = acc; acc += g_counts[e]; }
        g_offsets[NUM_EXPERTS] = acc;
        int nt = 0;
        for (int e = 0; e < NUM_EXPERTS; e++) {
            int cnt = g_counts[e];
            for (int m0 = 0; m0 < cnt; m0 += BM) {
                g_tile_e[nt] = e;
                g_tile_m0[nt] = m0;
                nt++;
            }
        }
        g_ntiles = nt;
    }
}
__global__ void k_scatter() {
    int t = blockIdx.x * blockDim.x + threadIdx.x;
    if (t >= NUM_TOKENS) return;
#pragma unroll
    for (int k = 0; k < 2; k++) {
        int e = g_expert_of[2 * t + k];
        int pos = g_offsets[e] + atomicAdd(&g_cursor[e], 1);
        g_rowmap[pos] = t;
        g_gate_by_row[pos] = g_gate_of[2 * t + k];
    }
}

// ---------------- fp32 -> fp16 / zero-out ---------------------------------------
__global__ void k_cvt(const float4* __restrict__ src, uint2* __restrict__ dst,
                      size_t n4) {
    size_t i = (size_t)blockIdx.x * blockDim.x + threadIdx.x;
    if (i >= n4) return;
    float4 v = src[i];
    uint2 o;
    o.x = h2u(v.x, v.y);
    o.y = h2u(v.z, v.w);
    dst[i] = o;
}
__global__ void k_zero(float4* __restrict__ out) {
    size_t i = (size_t)blockIdx.x * blockDim.x + threadIdx.x;
    if (i < (size_t)NUM_TOKENS * HIDDEN / 4)
        out[i] = make_float4(0.f, 0.f, 0.f, 0.f);
}

// ---------------- GEMM1: act = silu(X@Wg^T+bg) * (X@Wu^T+bu) -------------------
// Extra blockIdx.y slices [MAXTILES, MAXTILES+CVT_SLICES) convert w2 fp32->fp16
// concurrently (GEMM1 does not read g_w2h; GEMM2 runs after this kernel).
__global__ __launch_bounds__(256, 2) void k_gemm1(const float* __restrict__ w13b,
                                                  const float4* __restrict__ w2src) {
    int ty = blockIdx.y;
    int tid = threadIdx.x;

    if (ty >= MAXTILES) {                    // w2 conversion CTA
        const size_t n4 = (size_t)NUM_EXPERTS * HIDDEN * INTER / 4;
        const size_t stride = (size_t)CVT_SLICES * NT1 * 256;
        size_t i = ((size_t)(ty - MAXTILES) * gridDim.x + blockIdx.x) * 256 + tid;
        uint2* dst = (uint2*)g_w2h;
        for (; i < n4; i += stride) {
            float4 v = w2src[i];
            uint2 o;
            o.x = h2u(v.x, v.y);
            o.y = h2u(v.z, v.w);
            dst[i] = o;
        }
        return;
    }
    if (ty >= g_ntiles) return;

    extern __shared__ __align__(128) uint8_t smem[];
    int* stok = (int*)smem;
    float* sbias = (float*)(smem + 512);
    uint32_t sb = smem_u32(smem);
    uint32_t stage0 = sb + 1024;

    int e = g_tile_e[ty];
    int m0 = g_tile_m0[ty];
    int seg0 = g_offsets[e];
    int cnt  = g_offsets[e + 1] - seg0;
    int n0 = blockIdx.x * BN1;
    int wid = tid >> 5, lid = tid & 31;
    int warpM = wid & 3, warpN = wid >> 2;

    if (tid < BM) {
        int m = m0 + tid;
        stok[tid] = g_rowmap[seg0 + (m < cnt ? m : cnt - 1)];
    }
    if (tid >= 128 && tid < 192)
        sbias[tid - 128] = w13b[(size_t)e * N1 + n0 + (tid - 128)];
    else if (tid >= 192)
        sbias[tid - 192 + 64] = w13b[(size_t)e * N1 + INTER + n0 + (tid - 192)];
    __syncthreads();

    const __half* wg = g_w13h + (size_t)e * N1 * HIDDEN + (size_t)n0 * HIDDEN;
    const __half* wu = g_w13h + (size_t)e * N1 * HIDDEN + (size_t)(INTER + n0) * HIDDEN;

    auto load_stage = [&](int s, int c) {
        uint32_t st = stage0 + s * STG1;
        int k0 = c * BK;
#pragma unroll
        for (int q = 0; q < 8; q++) {
            int ch = tid + q * 256;          // 0..2047
            if (ch < 1024) {                 // A: 128 rows x 8 chunks of 16B
                int r = ch >> 3, c8 = ch & 7;
                const __half* src = g_hsh + (size_t)stok[r] * HIDDEN + k0 + c8 * 8;
                CP16(st + r * PITCHB + c8 * 16, src);
            } else if (ch < 1536) {          // Bg: 64 rows x 8
                int i = ch - 1024, r = i >> 3, c8 = i & 7;
                const __half* src = wg + (size_t)r * HIDDEN + k0 + c8 * 8;
                CP16(st + A_BYTES + r * PITCHB + c8 * 16, src);
            } else {                         // Bu
                int i = ch - 1536, r = i >> 3, c8 = i & 7;
                const __half* src = wu + (size_t)r * HIDDEN + k0 + c8 * 8;
                CP16(st + A_BYTES + B1_BYTES + r * PITCHB + c8 * 16, src);
            }
        }
        CP_COMMIT();
    };

    float accG[2][4][4], accU[2][4][4];
#pragma unroll
    for (int i = 0; i < 2; i++)
#pragma unroll
        for (int j = 0; j < 4; j++)
#pragma unroll
            for (int q = 0; q < 4; q++) { accG[i][j][q] = 0.f; accU[i][j][q] = 0.f; }

    load_stage(0, 0);
    load_stage(1, 1);

    int lrow = lid & 15;
    int lcolb = (lid & 16);                  // 0 or 16 bytes

    for (int c = 0; c < NC; c++) {
        CP_WAIT1();
        __syncthreads();
        if (c + 2 < NC) load_stage((c + 2) % 3, c + 2);
        else CP_COMMIT();                    // keep group ledger advancing (tail)
        uint32_t st = stage0 + (c % 3) * STG1;
        uint32_t aBase = st + (warpM * 32 + lrow) * PITCHB + lcolb;
        uint32_t gBase = st + A_BYTES + (warpN * 32 + lrow) * PITCHB + lcolb;
        uint32_t uBase = gBase + B1_BYTES;
#pragma unroll
        for (int kk = 0; kk < 4; kk++) {     // four k16 steps
            uint32_t koff = kk * 32;
            uint32_t a[2][4];
            ldsm4(a[0][0], a[0][1], a[0][2], a[0][3], aBase + koff);
            ldsm4(a[1][0], a[1][1], a[1][2], a[1][3], aBase + 16 * PITCHB + koff);
#pragma unroll
            for (int ntp = 0; ntp < 2; ntp++) {
                uint32_t b0, b1, b2, b3;
                ldsm4(b0, b1, b2, b3, gBase + ntp * 16 * PITCHB + koff);
#pragma unroll
                for (int mt = 0; mt < 2; mt++) {
                    mma16816(accG[mt][2 * ntp + 0], a[mt][0], a[mt][1], a[mt][2], a[mt][3], b0, b2);
                    mma16816(accG[mt][2 * ntp + 1], a[mt][0], a[mt][1], a[mt][2], a[mt][3], b1, b3);
                }
                ldsm4(b0, b1, b2, b3, uBase + ntp * 16 * PITCHB + koff);
#pragma unroll
                for (int mt = 0; mt < 2; mt++) {
                    mma16816(accU[mt][2 * ntp + 0], a[mt][0], a[mt][1], a[mt][2], a[mt][3], b0, b2);
                    mma16816(accU[mt][2 * ntp + 1], a[mt][0], a[mt][1], a[mt][2], a[mt][3], b1, b3);
                }
            }
        }
    }

    int g = lid >> 2, t = lid & 3;
#pragma unroll
    for (int mt = 0; mt < 2; mt++) {
#pragma unroll
        for (int nt = 0; nt < 4; nt++) {
            int ncol = warpN * 32 + nt * 8 + 2 * t;
            float bg0 = sbias[ncol], bg1 = sbias[ncol + 1];
            float bu0 = sbias[64 + ncol], bu1 = sbias[64 + ncol + 1];
            int mA = m0 + warpM * 32 + mt * 16 + g;
            int mB = mA + 8;
            if (mA < cnt) {
                float a0 = silu(accG[mt][nt][0] + bg0) * (accU[mt][nt][0] + bu0);
                float a1 = silu(accG[mt][nt][1] + bg1) * (accU[mt][nt][1] + bu1);
                *(uint32_t*)(g_acth + (size_t)(seg0 + mA) * INTER + n0 + ncol) = h2u(a0, a1);
            }
            if (mB < cnt) {
                float a2 = silu(accG[mt][nt][2] + bg0) * (accU[mt][nt][2] + bu0);
                float a3 = silu(accG[mt][nt][3] + bg1) * (accU[mt][nt][3] + bu1);
                *(uint32_t*)(g_acth + (size_t)(seg0 + mB) * INTER + n0 + ncol) = h2u(a2, a3);
            }
        }
    }
}

// ---------------- GEMM2: out += gate * (act @ W2^T + b2), fused combine --------
__global__ __launch_bounds__(256, 2) void k_gemm2(const float* __restrict__ w2b,
                                                  float* __restrict__ out) {
    extern __shared__ __align__(128) uint8_t smem[];
    float* sbias = (float*)(smem + 512);
    uint32_t sb = smem_u32(smem);
    uint32_t stage0 = sb + 1024;

    int ty = blockIdx.y;
    if (ty >= g_ntiles) return;
    int e = g_tile_e[ty];
    int m0 = g_tile_m0[ty];
    int seg0 = g_offsets[e];
    int cnt  = g_offsets[e + 1] - seg0;
    int n0 = blockIdx.x * BN2;
    int tid = threadIdx.x, wid = tid >> 5, lid = tid & 31;
    int warpM = wid & 3, warpN = wid >> 2;

    if (tid < BN2) sbias[tid] = w2b[(size_t)e * HIDDEN + n0 + tid];
    __syncthreads();

    const __half* wb = g_w2h + (size_t)e * HIDDEN * INTER + (size_t)n0 * INTER;
    const __half* aext = g_acth + (size_t)seg0 * INTER;
    int mclamp = cnt - 1;

    auto load_stage = [&](int s, int c) {
        uint32_t st = stage0 + s * STG2;
        int k0 = c * BK;
#pragma unroll
        for (int q = 0; q < 7; q++) {
            int ch = tid + q * 256;          // 0..1791
            if (ch < 1024) {                 // A: 128 rows x 8
                int r = ch >> 3, c8 = ch & 7;
                int m = m0 + r; if (m > mclamp) m = mclamp;
                const __half* src = aext + (size_t)m * INTER + k0 + c8 * 8;
                CP16(st + r * PITCHB + c8 * 16, src);
            } else {                         // B: 96 rows x 8
                int i = ch - 1024, r = i >> 3, c8 = i & 7;
                const __half* src = wb + (size_t)r * INTER + k0 + c8 * 8;
                CP16(st + A_BYTES + r * PITCHB + c8 * 16, src);
            }
        }
        CP_COMMIT();
    };

    float acc[2][6][4];
#pragma unroll
    for (int i = 0; i < 2; i++)
#pragma unroll
        for (int j = 0; j < 6; j++)
#pragma unroll
            for (int q = 0; q < 4; q++) acc[i][j][q] = 0.f;

    load_stage(0, 0);
    load_stage(1, 1);

    int lrow = lid & 15;
    int lcolb = (lid & 16);

    for (int c = 0; c < NC; c++) {
        CP_WAIT1();
        __syncthreads();
        if (c + 2 < NC) load_stage((c + 2) % 3, c + 2);
        else CP_COMMIT();                    // keep group ledger advancing (tail)
        uint32_t st = stage0 + (c % 3) * STG2;
        uint32_t aBase = st + (warpM * 32 + lrow) * PITCHB + lcolb;
        uint32_t bBase = st + A_BYTES + (warpN * 48 + lrow) * PITCHB + lcolb;
#pragma unroll
        for (int kk = 0; kk < 4; kk++) {
            uint32_t koff = kk * 32;
            uint32_t a[2][4];
            ldsm4(a[0][0], a[0][1], a[0][2], a[0][3], aBase + koff);
            ldsm4(a[1][0], a[1][1], a[1][2], a[1][3], aBase + 16 * PITCHB + koff);
#pragma unroll
            for (int ntp = 0; ntp < 3; ntp++) {
                uint32_t b0, b1, b2, b3;
                ldsm4(b0, b1, b2, b3, bBase + ntp * 16 * PITCHB + koff);
#pragma unroll
                for (int mt = 0; mt < 2; mt++) {
                    mma16816(acc[mt][2 * ntp + 0], a[mt][0], a[mt][1], a[mt][2], a[mt][3], b0, b2);
                    mma16816(acc[mt][2 * ntp + 1], a[mt][0], a[mt][1], a[mt][2], a[mt][3], b1, b3);
                }
            }
        }
    }

    // fused combine epilogue: out[token] += gate * (acc + bias)
    int g = lid >> 2, t = lid & 3;
#pragma unroll
    for (int mt = 0; mt < 2; mt++) {
        int mA = m0 + warpM * 32 + mt * 16 + g;
        int mB = mA + 8;
        int tokA = 0, tokB = 0;
        float gA = 0.f, gB = 0.f;
        if (mA < cnt) { tokA = g_rowmap[seg0 + mA]; gA = g_gate_by_row[seg0 + mA]; }
        if (mB < cnt) { tokB = g_rowmap[seg0 + mB]; gB = g_gate_by_row[seg0 + mB]; }
#pragma unroll
        for (int nt = 0; nt < 6; nt++) {
            int ncol = warpN * 48 + nt * 8 + 2 * t;
            float b0 = sbias[ncol], b1 = sbias[ncol + 1];
            if (mA < cnt) {
                float* d = out + (size_t)tokA * HIDDEN + n0 + ncol;
                atomicAdd(d + 0, gA * (acc[mt][nt][0] + b0));
                atomicAdd(d + 1, gA * (acc[mt][nt][1] + b1));
            }
            if (mB < cnt) {
                float* d = out + (size_t)tokB * HIDDEN + n0 + ncol;
                atomicAdd(d + 0, gB * (acc[mt][nt][2] + b0));
                atomicAdd(d + 1, gB * (acc[mt][nt][3] + b1));
            }
        }
    }
}

// ---------------- launch ---------------------------------------------------------
extern "C" void kernel_launch(void* const* d_in, const int* in_sizes, int n_in,
                              void* d_out, int out_size)
{
    const float* hs   = (const float*)d_in[0];
    const float* rl   = (const float*)d_in[1];
    const float* w13  = (const float*)d_in[2];
    const float* w2   = (const float*)d_in[3];
    const float* w13b = (const float*)d_in[4];
    const float* w2b  = (const float*)d_in[5];
    float* out = (float*)d_out;

    static bool attr_done = false;
    if (!attr_done) {
        cudaFuncSetAttribute(k_gemm1, cudaFuncAttributeMaxDynamicSharedMemorySize, G1_SMEM);
        cudaFuncSetAttribute(k_gemm2, cudaFuncAttributeMaxDynamicSharedMemorySize, G2_SMEM);
        attr_done = true;
    }

    k_init<<<1, 32>>>();
    k_route<<<(NUM_TOKENS + 255) / 256, 256>>>(rl);
    k_scan<<<1, 1>>>();
    k_scatter<<<(NUM_TOKENS + 255) / 256, 256>>>();

    {
        size_t n4 = (size_t)NUM_TOKENS * HIDDEN / 4;
        k_zero<<<(unsigned)((n4 + 255) / 256), 256>>>((float4*)out);
    }

    __half* w13h_ptr = nullptr;  cudaGetSymbolAddress((void**)&w13h_ptr, g_w13h);
    __half* hsh_ptr  = nullptr;  cudaGetSymbolAddress((void**)&hsh_ptr,  g_hsh);

    {
        size_t n4 = (size_t)NUM_EXPERTS * N1 * HIDDEN / 4;
        k_cvt<<<(unsigned)((n4 + 255) / 256), 256>>>((const float4*)w13, (uint2*)w13h_ptr, n4);
    }
    {
        size_t n4 = (size_t)NUM_TOKENS * HIDDEN / 4;
        k_cvt<<<(unsigned)((n4 + 255) / 256), 256>>>((const float4*)hs, (uint2*)hsh_ptr, n4);
    }

    {   // GEMM1 + concurrent w2 conversion (extra y-slices)
        dim3 grid(NT1, MAXTILES + CVT_SLICES);
        k_gemm1<<<grid, 256, G1_SMEM>>>(w13b, (const float4*)w2);
    }
    {   // GEMM2 with fused gate-combine into out
        dim3 grid(NT2, MAXTILES);
        k_gemm2<<<grid, 256, G2_SMEM>>>(w2b, out);
    }
}